// round 1
// baseline (speedup 1.0000x reference)
#include <cuda_runtime.h>
#include <math.h>

// Problem constants
#define B_  4
#define T_  2048
#define S_  2048
#define C_  512
#define H_  16
#define D_  32

// Scratch (device globals: no allocations allowed)
__device__ float g_Q[(size_t)B_*H_*T_*D_];   // [B,H,T,D]
__device__ float g_K[(size_t)B_*H_*S_*D_];   // [B,H,S,D]
__device__ float g_V[(size_t)B_*H_*S_*D_];   // [B,H,S,D]
__device__ float g_AO[(size_t)B_*T_*C_];     // [B,T,C] attention output

// ---------------------------------------------------------------------------
// GEMM: C = A(M x 512) @ W(512 x 512) + bias
// SCATTER=1: write into [B,H,T,D] head-split layout; SCATTER=0: plain [M,512].
// 128x128 tile, BK=16, 256 threads, 8x8 per thread.
// ---------------------------------------------------------------------------
template<int SCATTER>
__global__ __launch_bounds__(256)
void gemm512_kernel(const float* __restrict__ A, const float* __restrict__ W,
                    const float* __restrict__ bias, float* __restrict__ C)
{
    __shared__ float As[16][128];   // [k][m]
    __shared__ float Bs[16][128];   // [k][n]

    const int bn = blockIdx.x * 128;
    const int bm = blockIdx.y * 128;
    const int tid = threadIdx.x;
    const int tx = tid & 15;        // 0..15  -> n
    const int ty = tid >> 4;        // 0..15  -> m

    float acc[8][8];
    #pragma unroll
    for (int i = 0; i < 8; i++)
        #pragma unroll
        for (int j = 0; j < 8; j++)
            acc[i][j] = 0.f;

    for (int k0 = 0; k0 < 512; k0 += 16) {
        // A tile: 128 rows x 16 k -> transpose into As[k][m]
        #pragma unroll
        for (int i = 0; i < 2; i++) {
            int id = i * 256 + tid;            // 0..511
            int r  = id >> 2;                  // 0..127
            int c4 = (id & 3) * 4;             // 0,4,8,12
            float4 v = *(const float4*)(A + (size_t)(bm + r) * 512 + k0 + c4);
            As[c4 + 0][r] = v.x;
            As[c4 + 1][r] = v.y;
            As[c4 + 2][r] = v.z;
            As[c4 + 3][r] = v.w;
        }
        // W tile: 16 k-rows x 128 n
        #pragma unroll
        for (int i = 0; i < 2; i++) {
            int id = i * 256 + tid;            // 0..511
            int r  = id >> 5;                  // 0..15
            int c4 = (id & 31) * 4;            // 0..124
            *(float4*)(&Bs[r][c4]) =
                *(const float4*)(W + (size_t)(k0 + r) * 512 + bn + c4);
        }
        __syncthreads();

        #pragma unroll
        for (int k = 0; k < 16; k++) {
            float a[8], b[8];
            *(float4*)&a[0] = *(const float4*)&As[k][ty * 8];
            *(float4*)&a[4] = *(const float4*)&As[k][ty * 8 + 4];
            *(float4*)&b[0] = *(const float4*)&Bs[k][tx * 8];
            *(float4*)&b[4] = *(const float4*)&Bs[k][tx * 8 + 4];
            #pragma unroll
            for (int i = 0; i < 8; i++)
                #pragma unroll
                for (int j = 0; j < 8; j++)
                    acc[i][j] += a[i] * b[j];
        }
        __syncthreads();
    }

    #pragma unroll
    for (int i = 0; i < 8; i++) {
        int row = bm + ty * 8 + i;
        #pragma unroll
        for (int j = 0; j < 8; j++) {
            int col = bn + tx * 8 + j;
            float v = acc[i][j] + bias[col];
            if (SCATTER) {
                int b = row >> 11;             // row / 2048
                int t = row & 2047;
                int h = col >> 5;              // col / 32
                int d = col & 31;
                C[(((size_t)(b * H_ + h)) * T_ + t) * D_ + d] = v;
            } else {
                C[(size_t)row * 512 + col] = v;
            }
        }
    }
}

// ---------------------------------------------------------------------------
// Flash attention: per (b,h): O = softmax(Q K^T * scale) V, D=32.
// One query per thread, 128 queries per block, K/V streamed in 32-row tiles.
// Output written directly into [B,T,C] layout for the final projection.
// ---------------------------------------------------------------------------
__global__ __launch_bounds__(128)
void attn_kernel(const float* __restrict__ Q, const float* __restrict__ K,
                 const float* __restrict__ V, float* __restrict__ O)
{
    const float scale = 0.1767766952966369f;   // 1/sqrt(32)

    const int bh = blockIdx.y;                 // b*H + h
    const int t  = blockIdx.x * 128 + threadIdx.x;

    const float* qp = Q + ((size_t)bh * T_ + t) * D_;
    float q[32];
    #pragma unroll
    for (int d = 0; d < 32; d++) q[d] = qp[d] * scale;

    float o[32];
    #pragma unroll
    for (int d = 0; d < 32; d++) o[d] = 0.f;
    float m = -INFINITY;
    float l = 0.f;

    __shared__ float ksh[32][32];
    __shared__ float vsh[32][32];

    const float* kbase = K + (size_t)bh * S_ * D_;
    const float* vbase = V + (size_t)bh * S_ * D_;

    for (int s0 = 0; s0 < S_; s0 += 32) {
        // Tile is 1024 contiguous floats in [B,H,S,D]; copy as float4.
        const float4* kg = (const float4*)(kbase + (size_t)s0 * D_);
        const float4* vg = (const float4*)(vbase + (size_t)s0 * D_);
        #pragma unroll
        for (int i = 0; i < 2; i++) {
            int id = i * 128 + threadIdx.x;    // 0..255
            ((float4*)ksh)[id] = kg[id];
            ((float4*)vsh)[id] = vg[id];
        }
        __syncthreads();

        float sc[32];
        float mx = m;
        #pragma unroll
        for (int j = 0; j < 32; j++) {
            const float4* kr = (const float4*)&ksh[j][0];
            float d0 = 0.f, d1 = 0.f, d2 = 0.f, d3 = 0.f;
            #pragma unroll
            for (int dd = 0; dd < 8; dd++) {
                float4 kv = kr[dd];
                d0 += q[dd * 4 + 0] * kv.x;
                d1 += q[dd * 4 + 1] * kv.y;
                d2 += q[dd * 4 + 2] * kv.z;
                d3 += q[dd * 4 + 3] * kv.w;
            }
            float dot = (d0 + d1) + (d2 + d3);
            sc[j] = dot;
            mx = fmaxf(mx, dot);
        }

        float corr = __expf(m - mx);           // 0 on first tile (m=-inf)
        l *= corr;
        #pragma unroll
        for (int d = 0; d < 32; d++) o[d] *= corr;

        #pragma unroll
        for (int j = 0; j < 32; j++) {
            float p = __expf(sc[j] - mx);
            l += p;
            const float4* vr = (const float4*)&vsh[j][0];
            #pragma unroll
            for (int dd = 0; dd < 8; dd++) {
                float4 vv = vr[dd];
                o[dd * 4 + 0] += p * vv.x;
                o[dd * 4 + 1] += p * vv.y;
                o[dd * 4 + 2] += p * vv.z;
                o[dd * 4 + 3] += p * vv.w;
            }
        }
        m = mx;
        __syncthreads();
    }

    const float inv = 1.f / l;
    const int b = bh >> 4;                     // bh / H
    const int h = bh & 15;
    float* op = O + ((size_t)(b * T_ + t)) * C_ + h * D_;
    #pragma unroll
    for (int dd = 0; dd < 8; dd++) {
        float4 v;
        v.x = o[dd * 4 + 0] * inv;
        v.y = o[dd * 4 + 1] * inv;
        v.z = o[dd * 4 + 2] * inv;
        v.w = o[dd * 4 + 3] * inv;
        ((float4*)op)[dd] = v;
    }
}

// ---------------------------------------------------------------------------
// Launch
// ---------------------------------------------------------------------------
extern "C" void kernel_launch(void* const* d_in, const int* in_sizes, int n_in,
                              void* d_out, int out_size)
{
    const float* x   = (const float*)d_in[0];
    const float* ctx = (const float*)d_in[1];
    const float* Wq  = (const float*)d_in[2];
    const float* bq  = (const float*)d_in[3];
    const float* Wk  = (const float*)d_in[4];
    const float* bk  = (const float*)d_in[5];
    const float* Wv  = (const float*)d_in[6];
    const float* bv  = (const float*)d_in[7];
    const float* Wo  = (const float*)d_in[8];
    const float* bo  = (const float*)d_in[9];
    float* out = (float*)d_out;

    float *Qp, *Kp, *Vp, *AOp;
    cudaGetSymbolAddress((void**)&Qp,  g_Q);
    cudaGetSymbolAddress((void**)&Kp,  g_K);
    cudaGetSymbolAddress((void**)&Vp,  g_V);
    cudaGetSymbolAddress((void**)&AOp, g_AO);

    dim3 gemmGrid(C_ / 128, (B_ * T_) / 128);   // (4, 64)
    gemm512_kernel<1><<<gemmGrid, 256>>>(x,   Wq, bq, Qp);
    gemm512_kernel<1><<<gemmGrid, 256>>>(ctx, Wk, bk, Kp);
    gemm512_kernel<1><<<gemmGrid, 256>>>(ctx, Wv, bv, Vp);

    dim3 attnGrid(T_ / 128, B_ * H_);           // (16, 64)
    attn_kernel<<<attnGrid, 128>>>(Qp, Kp, Vp, AOp);

    gemm512_kernel<0><<<gemmGrid, 256>>>(AOp, Wo, bo, out);
}

// round 3
// speedup vs baseline: 3.2280x; 3.2280x over previous
#include <cuda_runtime.h>
#include <cuda_bf16.h>
#include <math.h>
#include <stdint.h>

// Problem constants
#define B_  4
#define T_  2048
#define S_  2048
#define C_  512
#define H_  16
#define D_  32

// Scratch (device globals: no allocations allowed)
__device__ float g_Q[(size_t)B_*H_*T_*D_];   // [B,H,T,D]
__device__ float g_K[(size_t)B_*H_*S_*D_];   // [B,H,S,D]
__device__ float g_V[(size_t)B_*H_*S_*D_];   // [B,H,S,D]
__device__ float g_AO[(size_t)B_*T_*C_];     // [B,T,C]

// ===========================================================================
// Helpers: ldmatrix + mma.sync (compute_103-base-safe, sm_80-era PTX)
// ===========================================================================
__device__ __forceinline__ uint32_t smem_u32(const void* p) {
    uint32_t a;
    asm("{ .reg .u64 t; cvta.to.shared.u64 t, %1; cvt.u32.u64 %0, t; }"
        : "=r"(a) : "l"(p));
    return a;
}

__device__ __forceinline__ void ldsm4(uint32_t addr, uint32_t& r0, uint32_t& r1,
                                      uint32_t& r2, uint32_t& r3) {
    asm volatile("ldmatrix.sync.aligned.m8n8.x4.shared.b16 {%0,%1,%2,%3}, [%4];"
                 : "=r"(r0), "=r"(r1), "=r"(r2), "=r"(r3) : "r"(addr));
}
__device__ __forceinline__ void ldsm4t(uint32_t addr, uint32_t& r0, uint32_t& r1,
                                       uint32_t& r2, uint32_t& r3) {
    asm volatile("ldmatrix.sync.aligned.m8n8.x4.trans.shared.b16 {%0,%1,%2,%3}, [%4];"
                 : "=r"(r0), "=r"(r1), "=r"(r2), "=r"(r3) : "r"(addr));
}

// D += A * B  (m16n8k16, bf16 in, fp32 accum)
__device__ __forceinline__ void mmabf(float* d, const uint32_t* a,
                                      uint32_t b0, uint32_t b1) {
    asm volatile("mma.sync.aligned.m16n8k16.row.col.f32.bf16.bf16.f32 "
                 "{%0,%1,%2,%3}, {%4,%5,%6,%7}, {%8,%9}, {%0,%1,%2,%3};"
                 : "+f"(d[0]), "+f"(d[1]), "+f"(d[2]), "+f"(d[3])
                 : "r"(a[0]), "r"(a[1]), "r"(a[2]), "r"(a[3]),
                   "r"(b0), "r"(b1));
}

__device__ __forceinline__ uint32_t bfpack(float x0, float x1) {
    __nv_bfloat162 t = __floats2bfloat162_rn(x0, x1);
    return *reinterpret_cast<uint32_t*>(&t);
}
// hi = bf16(x); lo = bf16(x - hi)   (packed pairs, x0 -> low half)
__device__ __forceinline__ void split2(float x0, float x1, uint32_t& hi, uint32_t& lo) {
    float h0 = __bfloat162float(__float2bfloat16(x0));
    float h1 = __bfloat162float(__float2bfloat16(x1));
    hi = bfpack(x0, x1);
    lo = bfpack(x0 - h0, x1 - h1);
}
__device__ __forceinline__ float ex2f(float x) {
    float y; asm("ex2.approx.ftz.f32 %0, %1;" : "=f"(y) : "f"(x)); return y;
}

// ===========================================================================
// GEMM: C = A(Mx512) @ W(512x512) + bias, 3-term bf16 split.
// CTA 128x64, 8 warps (4m x 2n), warp tile 32x32, K-chunk 32.
// SCATTER=1: write into [B,H,T,D] head-split layout.
// ===========================================================================
#define GLDA 40   // halfword stride (32 + 8 pad) -> conflict-free ldmatrix
#define GLDB 72   // halfword stride (64 + 8 pad)

template<int SCATTER>
__global__ __launch_bounds__(256)
void gemm_mma_kernel(const float* __restrict__ A, const float* __restrict__ W,
                     const float* __restrict__ bias, float* __restrict__ C)
{
    __shared__ uint16_t sAh[128 * GLDA], sAl[128 * GLDA];
    __shared__ uint16_t sBh[32 * GLDB],  sBl[32 * GLDB];

    const int tid = threadIdx.x;
    const int lane = tid & 31, wid = tid >> 5;
    const int g = lane >> 3, r = lane & 7;
    const int tq = lane >> 2, tc = lane & 3;
    const int wm = wid >> 1, wn = wid & 1;
    const int bm = blockIdx.y * 128, bn = blockIdx.x * 64;

    float acc[2][4][4];
    #pragma unroll
    for (int i = 0; i < 2; i++)
        #pragma unroll
        for (int j = 0; j < 4; j++)
            #pragma unroll
            for (int k = 0; k < 4; k++) acc[i][j][k] = 0.f;

    float4 ra[4], rb[2];
    #pragma unroll
    for (int i = 0; i < 4; ++i) {
        int id = i * 256 + tid, row = id >> 3, c4 = (id & 7) * 4;
        ra[i] = *(const float4*)(A + (size_t)(bm + row) * 512 + c4);
    }
    #pragma unroll
    for (int i = 0; i < 2; ++i) {
        int id = i * 256 + tid, k = id >> 4, n4 = (id & 15) * 4;
        rb[i] = *(const float4*)(W + (size_t)k * 512 + bn + n4);
    }

    const uint32_t bAh = smem_u32(sAh), bAl = smem_u32(sAl);
    const uint32_t bBh = smem_u32(sBh), bBl = smem_u32(sBl);

    for (int c = 0; c < 16; ++c) {
        // split + STS (A: [m][k] k-contig; B: [k][n] n-contig)
        #pragma unroll
        for (int i = 0; i < 4; ++i) {
            int id = i * 256 + tid, row = id >> 3, c4 = (id & 7) * 4;
            uint32_t h0, l0, h1, l1;
            split2(ra[i].x, ra[i].y, h0, l0);
            split2(ra[i].z, ra[i].w, h1, l1);
            *(uint2*)&sAh[row * GLDA + c4] = make_uint2(h0, h1);
            *(uint2*)&sAl[row * GLDA + c4] = make_uint2(l0, l1);
        }
        #pragma unroll
        for (int i = 0; i < 2; ++i) {
            int id = i * 256 + tid, k = id >> 4, n4 = (id & 15) * 4;
            uint32_t h0, l0, h1, l1;
            split2(rb[i].x, rb[i].y, h0, l0);
            split2(rb[i].z, rb[i].w, h1, l1);
            *(uint2*)&sBh[k * GLDB + n4] = make_uint2(h0, h1);
            *(uint2*)&sBl[k * GLDB + n4] = make_uint2(l0, l1);
        }
        __syncthreads();

        if (c < 15) {
            #pragma unroll
            for (int i = 0; i < 4; ++i) {
                int id = i * 256 + tid, row = id >> 3, c4 = (id & 7) * 4;
                ra[i] = *(const float4*)(A + (size_t)(bm + row) * 512 + (c + 1) * 32 + c4);
            }
            #pragma unroll
            for (int i = 0; i < 2; ++i) {
                int id = i * 256 + tid, k = id >> 4, n4 = (id & 15) * 4;
                rb[i] = *(const float4*)(W + (size_t)((c + 1) * 32 + k) * 512 + bn + n4);
            }
        }

        #pragma unroll
        for (int kb = 0; kb < 2; ++kb) {
            uint32_t ah[2][4], al[2][4];
            #pragma unroll
            for (int mf = 0; mf < 2; ++mf) {
                int row = wm * 32 + mf * 16 + (g & 1) * 8 + r;
                int hw  = kb * 16 + (g >> 1) * 8;
                uint32_t off = (uint32_t)(row * GLDA + hw) * 2;
                ldsm4(bAh + off, ah[mf][0], ah[mf][1], ah[mf][2], ah[mf][3]);
                ldsm4(bAl + off, al[mf][0], al[mf][1], al[mf][2], al[mf][3]);
            }
            #pragma unroll
            for (int nb = 0; nb < 2; ++nb) {
                int krow = kb * 16 + (g & 1) * 8 + r;
                int hw   = wn * 32 + nb * 16 + (g >> 1) * 8;
                uint32_t off = (uint32_t)(krow * GLDB + hw) * 2;
                uint32_t bh[4], bl[4];
                ldsm4t(bBh + off, bh[0], bh[1], bh[2], bh[3]);
                ldsm4t(bBl + off, bl[0], bl[1], bl[2], bl[3]);
                #pragma unroll
                for (int mf = 0; mf < 2; ++mf) {
                    #pragma unroll
                    for (int h2 = 0; h2 < 2; ++h2) {
                        float* d = acc[mf][nb * 2 + h2];
                        mmabf(d, ah[mf], bh[h2 * 2], bh[h2 * 2 + 1]);
                        mmabf(d, ah[mf], bl[h2 * 2], bl[h2 * 2 + 1]);
                        mmabf(d, al[mf], bh[h2 * 2], bh[h2 * 2 + 1]);
                    }
                }
            }
        }
        __syncthreads();
    }

    // epilogue
    #pragma unroll
    for (int mf = 0; mf < 2; ++mf) {
        int row0 = bm + wm * 32 + mf * 16 + tq;
        #pragma unroll
        for (int nf = 0; nf < 4; ++nf) {
            int col = bn + wn * 32 + nf * 8 + tc * 2;
            float b0v = bias[col], b1v = bias[col + 1];
            float2 v0 = make_float2(acc[mf][nf][0] + b0v, acc[mf][nf][1] + b1v);
            float2 v1 = make_float2(acc[mf][nf][2] + b0v, acc[mf][nf][3] + b1v);
            if (SCATTER) {
                int bb = row0 >> 11, t = row0 & 2047;
                int h = col >> 5, d = col & 31;
                *(float2*)&C[(((size_t)(bb * H_ + h)) * T_ + t) * D_ + d] = v0;
                *(float2*)&C[(((size_t)(bb * H_ + h)) * T_ + t + 8) * D_ + d] = v1;
            } else {
                *(float2*)&C[(size_t)row0 * 512 + col] = v0;
                *(float2*)&C[(size_t)(row0 + 8) * 512 + col] = v1;
            }
        }
    }
}

// ===========================================================================
// Flash attention on mma.sync: per (b,h): O = softmax(Q K^T * s) V
// CTA: 128 query rows (8 warps x 16), S-tiles of 64. 3-term bf16 splits.
// ===========================================================================
#define ALD 40

__global__ __launch_bounds__(256)
void attn_mma_kernel(const float* __restrict__ Q, const float* __restrict__ K,
                     const float* __restrict__ V, float* __restrict__ O)
{
    __shared__ uint16_t sm[10240];   // 20480 B, staged: Q(hi|lo) then K/V(hi|lo)

    const int tid = threadIdx.x, lane = tid & 31, wid = tid >> 5;
    const int g = lane >> 3, r = lane & 7;
    const int tq = lane >> 2, tc = lane & 3;
    const int bh = blockIdx.y, bidx = bh >> 4, hidx = bh & 15;
    const int t0 = blockIdx.x * 128;

    const uint32_t sb = smem_u32(sm);
    const uint32_t QHI = sb, QLO = sb + 10240;
    const uint32_t KHI = sb, KLO = sb + 5120, VHI = sb + 10240, VLO = sb + 15360;

    const float SC = 0.17677669529663689f * 1.4426950408889634f; // scale*log2e

    // ---- Q -> smem (prescaled hi/lo), then to registers ----
    #pragma unroll
    for (int i = 0; i < 4; ++i) {
        int id = i * 256 + tid, row = id >> 3, c4 = (id & 7) * 4;
        float4 v = *(const float4*)(Q + ((size_t)bh * T_ + t0 + row) * D_ + c4);
        uint32_t h0, l0, h1, l1;
        split2(v.x * SC, v.y * SC, h0, l0);
        split2(v.z * SC, v.w * SC, h1, l1);
        *(uint2*)&sm[row * ALD + c4]        = make_uint2(h0, h1);
        *(uint2*)&sm[5120 + row * ALD + c4] = make_uint2(l0, l1);
    }
    __syncthreads();
    uint32_t qh[2][4], ql[2][4];
    #pragma unroll
    for (int kb = 0; kb < 2; ++kb) {
        int row = wid * 16 + (g & 1) * 8 + r;
        int hw  = kb * 16 + (g >> 1) * 8;
        uint32_t off = (uint32_t)(row * ALD + hw) * 2;
        ldsm4(QHI + off, qh[kb][0], qh[kb][1], qh[kb][2], qh[kb][3]);
        ldsm4(QLO + off, ql[kb][0], ql[kb][1], ql[kb][2], ql[kb][3]);
    }
    __syncthreads();

    float o[4][4];
    #pragma unroll
    for (int i = 0; i < 4; i++)
        #pragma unroll
        for (int j = 0; j < 4; j++) o[i][j] = 0.f;
    float m0 = -INFINITY, m1 = -INFINITY, l0 = 0.f, l1 = 0.f;

    const float* Kb = K + (size_t)bh * S_ * D_;
    const float* Vb = V + (size_t)bh * S_ * D_;

    for (int s0 = 0; s0 < S_; s0 += 64) {
        float4 rk[2], rv[2];
        #pragma unroll
        for (int i = 0; i < 2; ++i) {
            int id = i * 256 + tid, row = id >> 3, c4 = (id & 7) * 4;
            rk[i] = *(const float4*)(Kb + (size_t)(s0 + row) * D_ + c4);
            rv[i] = *(const float4*)(Vb + (size_t)(s0 + row) * D_ + c4);
        }
        __syncthreads();   // prior tile's ldmatrix complete
        #pragma unroll
        for (int i = 0; i < 2; ++i) {
            int id = i * 256 + tid, row = id >> 3, c4 = (id & 7) * 4;
            uint32_t h0, lo0, h1, lo1;
            split2(rk[i].x, rk[i].y, h0, lo0);
            split2(rk[i].z, rk[i].w, h1, lo1);
            *(uint2*)&sm[row * ALD + c4]        = make_uint2(h0, h1);
            *(uint2*)&sm[2560 + row * ALD + c4] = make_uint2(lo0, lo1);
            split2(rv[i].x, rv[i].y, h0, lo0);
            split2(rv[i].z, rv[i].w, h1, lo1);
            *(uint2*)&sm[5120 + row * ALD + c4] = make_uint2(h0, h1);
            *(uint2*)&sm[7680 + row * ALD + c4] = make_uint2(lo0, lo1);
        }
        __syncthreads();

        // ---- S = Q K^T ----
        float s[8][4];
        #pragma unroll
        for (int j = 0; j < 8; j++)
            #pragma unroll
            for (int k = 0; k < 4; k++) s[j][k] = 0.f;

        #pragma unroll
        for (int kb = 0; kb < 2; ++kb) {
            #pragma unroll
            for (int nb = 0; nb < 4; ++nb) {
                int row = nb * 16 + (g >> 1) * 8 + r;    // s index
                int hw  = kb * 16 + (g & 1) * 8;         // d index
                uint32_t off = (uint32_t)(row * ALD + hw) * 2;
                uint32_t kh[4], kl[4];
                ldsm4(KHI + off, kh[0], kh[1], kh[2], kh[3]);
                ldsm4(KLO + off, kl[0], kl[1], kl[2], kl[3]);
                mmabf(s[nb * 2],     qh[kb], kh[0], kh[1]);
                mmabf(s[nb * 2 + 1], qh[kb], kh[2], kh[3]);
                mmabf(s[nb * 2],     qh[kb], kl[0], kl[1]);
                mmabf(s[nb * 2 + 1], qh[kb], kl[2], kl[3]);
                mmabf(s[nb * 2],     ql[kb], kh[0], kh[1]);
                mmabf(s[nb * 2 + 1], ql[kb], kh[2], kh[3]);
            }
        }

        // ---- online softmax (base-2 domain) ----
        float mx0 = m0, mx1 = m1;
        #pragma unroll
        for (int j = 0; j < 8; ++j) {
            mx0 = fmaxf(mx0, fmaxf(s[j][0], s[j][1]));
            mx1 = fmaxf(mx1, fmaxf(s[j][2], s[j][3]));
        }
        mx0 = fmaxf(mx0, __shfl_xor_sync(0xffffffffu, mx0, 1));
        mx0 = fmaxf(mx0, __shfl_xor_sync(0xffffffffu, mx0, 2));
        mx1 = fmaxf(mx1, __shfl_xor_sync(0xffffffffu, mx1, 1));
        mx1 = fmaxf(mx1, __shfl_xor_sync(0xffffffffu, mx1, 2));
        float c0 = ex2f(m0 - mx0), c1 = ex2f(m1 - mx1);
        m0 = mx0; m1 = mx1;

        float sum0 = 0.f, sum1 = 0.f;
        uint32_t ph[8][2], pl[8][2];
        #pragma unroll
        for (int j = 0; j < 8; ++j) {
            float p0 = ex2f(s[j][0] - m0);
            float p1 = ex2f(s[j][1] - m0);
            float p2 = ex2f(s[j][2] - m1);
            float p3 = ex2f(s[j][3] - m1);
            sum0 += p0 + p1; sum1 += p2 + p3;
            split2(p0, p1, ph[j][0], pl[j][0]);
            split2(p2, p3, ph[j][1], pl[j][1]);
        }
        sum0 += __shfl_xor_sync(0xffffffffu, sum0, 1);
        sum0 += __shfl_xor_sync(0xffffffffu, sum0, 2);
        sum1 += __shfl_xor_sync(0xffffffffu, sum1, 1);
        sum1 += __shfl_xor_sync(0xffffffffu, sum1, 2);
        l0 = l0 * c0 + sum0;
        l1 = l1 * c1 + sum1;
        #pragma unroll
        for (int nf = 0; nf < 4; ++nf) {
            o[nf][0] *= c0; o[nf][1] *= c0; o[nf][2] *= c1; o[nf][3] *= c1;
        }

        // ---- O += P V ----
        #pragma unroll
        for (int kb = 0; kb < 4; ++kb) {
            uint32_t aH[4] = { ph[2 * kb][0], ph[2 * kb][1], ph[2 * kb + 1][0], ph[2 * kb + 1][1] };
            uint32_t aL[4] = { pl[2 * kb][0], pl[2 * kb][1], pl[2 * kb + 1][0], pl[2 * kb + 1][1] };
            #pragma unroll
            for (int nb = 0; nb < 2; ++nb) {
                int row = kb * 16 + (g & 1) * 8 + r;     // s index (k of PV)
                int hw  = nb * 16 + (g >> 1) * 8;        // d index (n of PV)
                uint32_t off = (uint32_t)(row * ALD + hw) * 2;
                uint32_t vh[4], vl[4];
                ldsm4t(VHI + off, vh[0], vh[1], vh[2], vh[3]);
                ldsm4t(VLO + off, vl[0], vl[1], vl[2], vl[3]);
                mmabf(o[nb * 2],     aH, vh[0], vh[1]);
                mmabf(o[nb * 2 + 1], aH, vh[2], vh[3]);
                mmabf(o[nb * 2],     aH, vl[0], vl[1]);
                mmabf(o[nb * 2 + 1], aH, vl[2], vl[3]);
                mmabf(o[nb * 2],     aL, vh[0], vh[1]);
                mmabf(o[nb * 2 + 1], aL, vh[2], vh[3]);
            }
        }
    }

    // ---- finalize + store into [B,T,C] ----
    float i0 = 1.f / l0, i1 = 1.f / l1;
    int row = t0 + wid * 16 + tq;
    #pragma unroll
    for (int nf = 0; nf < 4; ++nf) {
        int col = hidx * 32 + nf * 8 + tc * 2;
        float2 v0 = make_float2(o[nf][0] * i0, o[nf][1] * i0);
        float2 v1 = make_float2(o[nf][2] * i1, o[nf][3] * i1);
        *(float2*)&O[((size_t)(bidx * T_ + row)) * C_ + col] = v0;
        *(float2*)&O[((size_t)(bidx * T_ + row + 8)) * C_ + col] = v1;
    }
}

// ===========================================================================
// Launch
// ===========================================================================
extern "C" void kernel_launch(void* const* d_in, const int* in_sizes, int n_in,
                              void* d_out, int out_size)
{
    const float* x   = (const float*)d_in[0];
    const float* ctx = (const float*)d_in[1];
    const float* Wq  = (const float*)d_in[2];
    const float* bq  = (const float*)d_in[3];
    const float* Wk  = (const float*)d_in[4];
    const float* bk  = (const float*)d_in[5];
    const float* Wv  = (const float*)d_in[6];
    const float* bv  = (const float*)d_in[7];
    const float* Wo  = (const float*)d_in[8];
    const float* bo  = (const float*)d_in[9];
    float* out = (float*)d_out;

    float *Qp, *Kp, *Vp, *AOp;
    cudaGetSymbolAddress((void**)&Qp,  g_Q);
    cudaGetSymbolAddress((void**)&Kp,  g_K);
    cudaGetSymbolAddress((void**)&Vp,  g_V);
    cudaGetSymbolAddress((void**)&AOp, g_AO);

    dim3 gemmGrid(C_ / 64, (B_ * T_) / 128);    // (8, 64)
    gemm_mma_kernel<1><<<gemmGrid, 256>>>(x,   Wq, bq, Qp);
    gemm_mma_kernel<1><<<gemmGrid, 256>>>(ctx, Wk, bk, Kp);
    gemm_mma_kernel<1><<<gemmGrid, 256>>>(ctx, Wv, bv, Vp);

    dim3 attnGrid(T_ / 128, B_ * H_);           // (16, 64)
    attn_mma_kernel<<<attnGrid, 256>>>(Qp, Kp, Vp, AOp);

    gemm_mma_kernel<0><<<gemmGrid, 256>>>(AOp, Wo, bo, out);
}

// round 4
// speedup vs baseline: 3.6222x; 1.1221x over previous
#include <cuda_runtime.h>
#include <cuda_bf16.h>
#include <math.h>
#include <stdint.h>

// Problem constants
#define B_  4
#define T_  2048
#define S_  2048
#define C_  512
#define H_  16
#define D_  32

// Scratch (device globals: no allocations allowed)
__device__ float g_Q[(size_t)B_*H_*T_*D_];   // [B,H,T,D]
__device__ float g_K[(size_t)B_*H_*S_*D_];   // [B,H,S,D]
__device__ float g_V[(size_t)B_*H_*S_*D_];   // [B,H,S,D]
__device__ float g_AO[(size_t)B_*T_*C_];     // [B,T,C]

// ===========================================================================
// Helpers: ldmatrix + mma.sync (compute_103-base-safe, sm_80-era PTX)
// ===========================================================================
__device__ __forceinline__ uint32_t smem_u32(const void* p) {
    uint32_t a;
    asm("{ .reg .u64 t; cvta.to.shared.u64 t, %1; cvt.u32.u64 %0, t; }"
        : "=r"(a) : "l"(p));
    return a;
}

__device__ __forceinline__ void ldsm4(uint32_t addr, uint32_t& r0, uint32_t& r1,
                                      uint32_t& r2, uint32_t& r3) {
    asm volatile("ldmatrix.sync.aligned.m8n8.x4.shared.b16 {%0,%1,%2,%3}, [%4];"
                 : "=r"(r0), "=r"(r1), "=r"(r2), "=r"(r3) : "r"(addr));
}
__device__ __forceinline__ void ldsm4t(uint32_t addr, uint32_t& r0, uint32_t& r1,
                                       uint32_t& r2, uint32_t& r3) {
    asm volatile("ldmatrix.sync.aligned.m8n8.x4.trans.shared.b16 {%0,%1,%2,%3}, [%4];"
                 : "=r"(r0), "=r"(r1), "=r"(r2), "=r"(r3) : "r"(addr));
}

// D += A * B  (m16n8k16, bf16 in, fp32 accum)
__device__ __forceinline__ void mmabf(float* d, const uint32_t* a,
                                      uint32_t b0, uint32_t b1) {
    asm volatile("mma.sync.aligned.m16n8k16.row.col.f32.bf16.bf16.f32 "
                 "{%0,%1,%2,%3}, {%4,%5,%6,%7}, {%8,%9}, {%0,%1,%2,%3};"
                 : "+f"(d[0]), "+f"(d[1]), "+f"(d[2]), "+f"(d[3])
                 : "r"(a[0]), "r"(a[1]), "r"(a[2]), "r"(a[3]),
                   "r"(b0), "r"(b1));
}

__device__ __forceinline__ uint32_t bfpack(float x0, float x1) {
    __nv_bfloat162 t = __floats2bfloat162_rn(x0, x1);
    return *reinterpret_cast<uint32_t*>(&t);
}
// hi = bf16(x); lo = bf16(x - hi)   (packed pairs, x0 -> low half)
__device__ __forceinline__ void split2(float x0, float x1, uint32_t& hi, uint32_t& lo) {
    float h0 = __bfloat162float(__float2bfloat16(x0));
    float h1 = __bfloat162float(__float2bfloat16(x1));
    hi = bfpack(x0, x1);
    lo = bfpack(x0 - h0, x1 - h1);
}
__device__ __forceinline__ float ex2f(float x) {
    float y; asm("ex2.approx.ftz.f32 %0, %1;" : "=f"(y) : "f"(x)); return y;
}

// ===========================================================================
// GEMM core: C = A(Mx512) @ W(512x512) + bias, 3-term bf16 split.
// CTA 128x64, 8 warps (4m x 2n), warp tile 32x32, K-chunk 32.
// SCATTER=1: write into [B,H,T,D] head-split layout.
// ===========================================================================
#define GLDA 40   // halfword stride (32 + 8 pad) -> conflict-free ldmatrix
#define GLDB 72   // halfword stride (64 + 8 pad)

template<int SCATTER>
__device__ __forceinline__
void gemm_body(const float* __restrict__ A, const float* __restrict__ W,
               const float* __restrict__ bias, float* __restrict__ C,
               int bm, int bn)
{
    __shared__ uint16_t sAh[128 * GLDA], sAl[128 * GLDA];
    __shared__ uint16_t sBh[32 * GLDB],  sBl[32 * GLDB];

    const int tid = threadIdx.x;
    const int lane = tid & 31, wid = tid >> 5;
    const int g = lane >> 3, r = lane & 7;
    const int tq = lane >> 2, tc = lane & 3;
    const int wm = wid >> 1, wn = wid & 1;

    float acc[2][4][4];
    #pragma unroll
    for (int i = 0; i < 2; i++)
        #pragma unroll
        for (int j = 0; j < 4; j++)
            #pragma unroll
            for (int k = 0; k < 4; k++) acc[i][j][k] = 0.f;

    float4 ra[4], rb[2];
    #pragma unroll
    for (int i = 0; i < 4; ++i) {
        int id = i * 256 + tid, row = id >> 3, c4 = (id & 7) * 4;
        ra[i] = *(const float4*)(A + (size_t)(bm + row) * 512 + c4);
    }
    #pragma unroll
    for (int i = 0; i < 2; ++i) {
        int id = i * 256 + tid, k = id >> 4, n4 = (id & 15) * 4;
        rb[i] = *(const float4*)(W + (size_t)k * 512 + bn + n4);
    }

    const uint32_t bAh = smem_u32(sAh), bAl = smem_u32(sAl);
    const uint32_t bBh = smem_u32(sBh), bBl = smem_u32(sBl);

    for (int c = 0; c < 16; ++c) {
        #pragma unroll
        for (int i = 0; i < 4; ++i) {
            int id = i * 256 + tid, row = id >> 3, c4 = (id & 7) * 4;
            uint32_t h0, l0, h1, l1;
            split2(ra[i].x, ra[i].y, h0, l0);
            split2(ra[i].z, ra[i].w, h1, l1);
            *(uint2*)&sAh[row * GLDA + c4] = make_uint2(h0, h1);
            *(uint2*)&sAl[row * GLDA + c4] = make_uint2(l0, l1);
        }
        #pragma unroll
        for (int i = 0; i < 2; ++i) {
            int id = i * 256 + tid, k = id >> 4, n4 = (id & 15) * 4;
            uint32_t h0, l0, h1, l1;
            split2(rb[i].x, rb[i].y, h0, l0);
            split2(rb[i].z, rb[i].w, h1, l1);
            *(uint2*)&sBh[k * GLDB + n4] = make_uint2(h0, h1);
            *(uint2*)&sBl[k * GLDB + n4] = make_uint2(l0, l1);
        }
        __syncthreads();

        if (c < 15) {
            #pragma unroll
            for (int i = 0; i < 4; ++i) {
                int id = i * 256 + tid, row = id >> 3, c4 = (id & 7) * 4;
                ra[i] = *(const float4*)(A + (size_t)(bm + row) * 512 + (c + 1) * 32 + c4);
            }
            #pragma unroll
            for (int i = 0; i < 2; ++i) {
                int id = i * 256 + tid, k = id >> 4, n4 = (id & 15) * 4;
                rb[i] = *(const float4*)(W + (size_t)((c + 1) * 32 + k) * 512 + bn + n4);
            }
        }

        #pragma unroll
        for (int kb = 0; kb < 2; ++kb) {
            uint32_t ah[2][4], al[2][4];
            #pragma unroll
            for (int mf = 0; mf < 2; ++mf) {
                int row = wm * 32 + mf * 16 + (g & 1) * 8 + r;
                int hw  = kb * 16 + (g >> 1) * 8;
                uint32_t off = (uint32_t)(row * GLDA + hw) * 2;
                ldsm4(bAh + off, ah[mf][0], ah[mf][1], ah[mf][2], ah[mf][3]);
                ldsm4(bAl + off, al[mf][0], al[mf][1], al[mf][2], al[mf][3]);
            }
            #pragma unroll
            for (int nb = 0; nb < 2; ++nb) {
                int krow = kb * 16 + (g & 1) * 8 + r;
                int hw   = wn * 32 + nb * 16 + (g >> 1) * 8;
                uint32_t off = (uint32_t)(krow * GLDB + hw) * 2;
                uint32_t bh[4], bl[4];
                ldsm4t(bBh + off, bh[0], bh[1], bh[2], bh[3]);
                ldsm4t(bBl + off, bl[0], bl[1], bl[2], bl[3]);
                #pragma unroll
                for (int mf = 0; mf < 2; ++mf) {
                    #pragma unroll
                    for (int h2 = 0; h2 < 2; ++h2) {
                        float* d = acc[mf][nb * 2 + h2];
                        mmabf(d, ah[mf], bh[h2 * 2], bh[h2 * 2 + 1]);
                        mmabf(d, ah[mf], bl[h2 * 2], bl[h2 * 2 + 1]);
                        mmabf(d, al[mf], bh[h2 * 2], bh[h2 * 2 + 1]);
                    }
                }
            }
        }
        __syncthreads();
    }

    #pragma unroll
    for (int mf = 0; mf < 2; ++mf) {
        int row0 = bm + wm * 32 + mf * 16 + tq;
        #pragma unroll
        for (int nf = 0; nf < 4; ++nf) {
            int col = bn + wn * 32 + nf * 8 + tc * 2;
            float b0v = bias[col], b1v = bias[col + 1];
            float2 v0 = make_float2(acc[mf][nf][0] + b0v, acc[mf][nf][1] + b1v);
            float2 v1 = make_float2(acc[mf][nf][2] + b0v, acc[mf][nf][3] + b1v);
            if (SCATTER) {
                int bb = row0 >> 11, t = row0 & 2047;
                int h = col >> 5, d = col & 31;
                *(float2*)&C[(((size_t)(bb * H_ + h)) * T_ + t) * D_ + d] = v0;
                *(float2*)&C[(((size_t)(bb * H_ + h)) * T_ + t + 8) * D_ + d] = v1;
            } else {
                *(float2*)&C[(size_t)row0 * 512 + col] = v0;
                *(float2*)&C[(size_t)(row0 + 8) * 512 + col] = v1;
            }
        }
    }
}

// Fused Q/K/V projection: blockIdx.z selects which GEMM (better wave packing).
__global__ __launch_bounds__(256)
void gemm_qkv_kernel(const float* __restrict__ x, const float* __restrict__ ctx,
                     const float* __restrict__ Wq, const float* __restrict__ bq,
                     const float* __restrict__ Wk, const float* __restrict__ bk,
                     const float* __restrict__ Wv, const float* __restrict__ bv,
                     float* __restrict__ Qo, float* __restrict__ Ko,
                     float* __restrict__ Vo)
{
    const int z = blockIdx.z;
    const float* A = (z == 0) ? x : ctx;
    const float* W = (z == 0) ? Wq : (z == 1) ? Wk : Wv;
    const float* bias = (z == 0) ? bq : (z == 1) ? bk : bv;
    float* C = (z == 0) ? Qo : (z == 1) ? Ko : Vo;
    gemm_body<1>(A, W, bias, C, blockIdx.y * 128, blockIdx.x * 64);
}

__global__ __launch_bounds__(256)
void gemm_out_kernel(const float* __restrict__ A, const float* __restrict__ W,
                     const float* __restrict__ bias, float* __restrict__ C)
{
    gemm_body<0>(A, W, bias, C, blockIdx.y * 128, blockIdx.x * 64);
}

// ===========================================================================
// Flash attention on mma.sync: per (b,h): O = softmax(Q K^T * s) V
// CTA: 128 query rows (8 warps x 16), S-tiles of 64. 3-term bf16 splits.
// Next K/V tile LDG issued right after STS (hidden under MMA phase);
// exp+split folded into the PV loop (lower register pressure).
// ===========================================================================
#define ALD 40

__global__ __launch_bounds__(256)
void attn_mma_kernel(const float* __restrict__ Q, const float* __restrict__ K,
                     const float* __restrict__ V, float* __restrict__ O)
{
    __shared__ uint16_t sm[10240];   // 20480 B, staged: Q(hi|lo) then K/V(hi|lo)

    const int tid = threadIdx.x, lane = tid & 31, wid = tid >> 5;
    const int g = lane >> 3, r = lane & 7;
    const int tq = lane >> 2, tc = lane & 3;
    const int bh = blockIdx.y, bidx = bh >> 4, hidx = bh & 15;
    const int t0 = blockIdx.x * 128;

    const uint32_t sb = smem_u32(sm);
    const uint32_t QHI = sb, QLO = sb + 10240;
    const uint32_t KHI = sb, KLO = sb + 5120, VHI = sb + 10240, VLO = sb + 15360;

    const float SC = 0.17677669529663689f * 1.4426950408889634f; // scale*log2e

    // ---- Q -> smem (prescaled hi/lo), then to registers ----
    #pragma unroll
    for (int i = 0; i < 4; ++i) {
        int id = i * 256 + tid, row = id >> 3, c4 = (id & 7) * 4;
        float4 v = *(const float4*)(Q + ((size_t)bh * T_ + t0 + row) * D_ + c4);
        uint32_t h0, l0, h1, l1;
        split2(v.x * SC, v.y * SC, h0, l0);
        split2(v.z * SC, v.w * SC, h1, l1);
        *(uint2*)&sm[row * ALD + c4]        = make_uint2(h0, h1);
        *(uint2*)&sm[5120 + row * ALD + c4] = make_uint2(l0, l1);
    }
    __syncthreads();
    uint32_t qh[2][4], ql[2][4];
    #pragma unroll
    for (int kb = 0; kb < 2; ++kb) {
        int row = wid * 16 + (g & 1) * 8 + r;
        int hw  = kb * 16 + (g >> 1) * 8;
        uint32_t off = (uint32_t)(row * ALD + hw) * 2;
        ldsm4(QHI + off, qh[kb][0], qh[kb][1], qh[kb][2], qh[kb][3]);
        ldsm4(QLO + off, ql[kb][0], ql[kb][1], ql[kb][2], ql[kb][3]);
    }

    float o[4][4];
    #pragma unroll
    for (int i = 0; i < 4; i++)
        #pragma unroll
        for (int j = 0; j < 4; j++) o[i][j] = 0.f;
    float m0 = -INFINITY, m1 = -INFINITY, l0 = 0.f, l1 = 0.f;

    const float* Kb = K + (size_t)bh * S_ * D_;
    const float* Vb = V + (size_t)bh * S_ * D_;

    // preload tile 0 into registers
    float4 rk[2], rv[2];
    #pragma unroll
    for (int i = 0; i < 2; ++i) {
        int id = i * 256 + tid, row = id >> 3, c4 = (id & 7) * 4;
        rk[i] = *(const float4*)(Kb + (size_t)row * D_ + c4);
        rv[i] = *(const float4*)(Vb + (size_t)row * D_ + c4);
    }

    for (int s0 = 0; s0 < S_; s0 += 64) {
        __syncthreads();   // prior tile's (or Q-phase) smem reads complete
        #pragma unroll
        for (int i = 0; i < 2; ++i) {
            int id = i * 256 + tid, row = id >> 3, c4 = (id & 7) * 4;
            uint32_t h0, lo0, h1, lo1;
            split2(rk[i].x, rk[i].y, h0, lo0);
            split2(rk[i].z, rk[i].w, h1, lo1);
            *(uint2*)&sm[row * ALD + c4]        = make_uint2(h0, h1);
            *(uint2*)&sm[2560 + row * ALD + c4] = make_uint2(lo0, lo1);
            split2(rv[i].x, rv[i].y, h0, lo0);
            split2(rv[i].z, rv[i].w, h1, lo1);
            *(uint2*)&sm[5120 + row * ALD + c4] = make_uint2(h0, h1);
            *(uint2*)&sm[7680 + row * ALD + c4] = make_uint2(lo0, lo1);
        }
        __syncthreads();

        // prefetch next tile (LDG latency hides under MMA phase below)
        if (s0 + 64 < S_) {
            #pragma unroll
            for (int i = 0; i < 2; ++i) {
                int id = i * 256 + tid, row = id >> 3, c4 = (id & 7) * 4;
                rk[i] = *(const float4*)(Kb + (size_t)(s0 + 64 + row) * D_ + c4);
                rv[i] = *(const float4*)(Vb + (size_t)(s0 + 64 + row) * D_ + c4);
            }
        }

        // ---- S = Q K^T ----
        float s[8][4];
        #pragma unroll
        for (int j = 0; j < 8; j++)
            #pragma unroll
            for (int k = 0; k < 4; k++) s[j][k] = 0.f;

        #pragma unroll
        for (int kb = 0; kb < 2; ++kb) {
            #pragma unroll
            for (int nb = 0; nb < 4; ++nb) {
                int row = nb * 16 + (g >> 1) * 8 + r;    // s index
                int hw  = kb * 16 + (g & 1) * 8;         // d index
                uint32_t off = (uint32_t)(row * ALD + hw) * 2;
                uint32_t kh[4], kl[4];
                ldsm4(KHI + off, kh[0], kh[1], kh[2], kh[3]);
                ldsm4(KLO + off, kl[0], kl[1], kl[2], kl[3]);
                mmabf(s[nb * 2],     qh[kb], kh[0], kh[1]);
                mmabf(s[nb * 2 + 1], qh[kb], kh[2], kh[3]);
                mmabf(s[nb * 2],     qh[kb], kl[0], kl[1]);
                mmabf(s[nb * 2 + 1], qh[kb], kl[2], kl[3]);
                mmabf(s[nb * 2],     ql[kb], kh[0], kh[1]);
                mmabf(s[nb * 2 + 1], ql[kb], kh[2], kh[3]);
            }
        }

        // ---- online softmax (base-2 domain) ----
        float mx0 = m0, mx1 = m1;
        #pragma unroll
        for (int j = 0; j < 8; ++j) {
            mx0 = fmaxf(mx0, fmaxf(s[j][0], s[j][1]));
            mx1 = fmaxf(mx1, fmaxf(s[j][2], s[j][3]));
        }
        mx0 = fmaxf(mx0, __shfl_xor_sync(0xffffffffu, mx0, 1));
        mx0 = fmaxf(mx0, __shfl_xor_sync(0xffffffffu, mx0, 2));
        mx1 = fmaxf(mx1, __shfl_xor_sync(0xffffffffu, mx1, 1));
        mx1 = fmaxf(mx1, __shfl_xor_sync(0xffffffffu, mx1, 2));
        float c0 = ex2f(m0 - mx0), c1 = ex2f(m1 - mx1);
        m0 = mx0; m1 = mx1;
        #pragma unroll
        for (int nf = 0; nf < 4; ++nf) {
            o[nf][0] *= c0; o[nf][1] *= c0; o[nf][2] *= c1; o[nf][3] *= c1;
        }

        // ---- O += P V (exp + split inlined per kb; only 8 p-regs live) ----
        float sum0 = 0.f, sum1 = 0.f;
        #pragma unroll
        for (int kb = 0; kb < 4; ++kb) {
            uint32_t aH[4], aL[4];
            #pragma unroll
            for (int jj = 0; jj < 2; ++jj) {
                int j = 2 * kb + jj;
                float p0 = ex2f(s[j][0] - m0);
                float p1 = ex2f(s[j][1] - m0);
                float p2 = ex2f(s[j][2] - m1);
                float p3 = ex2f(s[j][3] - m1);
                sum0 += p0 + p1; sum1 += p2 + p3;
                split2(p0, p1, aH[jj * 2],     aL[jj * 2]);
                split2(p2, p3, aH[jj * 2 + 1], aL[jj * 2 + 1]);
            }
            #pragma unroll
            for (int nb = 0; nb < 2; ++nb) {
                int row = kb * 16 + (g & 1) * 8 + r;     // s index (k of PV)
                int hw  = nb * 16 + (g >> 1) * 8;        // d index (n of PV)
                uint32_t off = (uint32_t)(row * ALD + hw) * 2;
                uint32_t vh[4], vl[4];
                ldsm4t(VHI + off, vh[0], vh[1], vh[2], vh[3]);
                ldsm4t(VLO + off, vl[0], vl[1], vl[2], vl[3]);
                mmabf(o[nb * 2],     aH, vh[0], vh[1]);
                mmabf(o[nb * 2 + 1], aH, vh[2], vh[3]);
                mmabf(o[nb * 2],     aH, vl[0], vl[1]);
                mmabf(o[nb * 2 + 1], aH, vl[2], vl[3]);
                mmabf(o[nb * 2],     aL, vh[0], vh[1]);
                mmabf(o[nb * 2 + 1], aL, vh[2], vh[3]);
            }
        }
        sum0 += __shfl_xor_sync(0xffffffffu, sum0, 1);
        sum0 += __shfl_xor_sync(0xffffffffu, sum0, 2);
        sum1 += __shfl_xor_sync(0xffffffffu, sum1, 1);
        sum1 += __shfl_xor_sync(0xffffffffu, sum1, 2);
        l0 = l0 * c0 + sum0;
        l1 = l1 * c1 + sum1;
    }

    // ---- finalize + store into [B,T,C] ----
    float i0 = 1.f / l0, i1 = 1.f / l1;
    int row = t0 + wid * 16 + tq;
    #pragma unroll
    for (int nf = 0; nf < 4; ++nf) {
        int col = hidx * 32 + nf * 8 + tc * 2;
        float2 v0 = make_float2(o[nf][0] * i0, o[nf][1] * i0);
        float2 v1 = make_float2(o[nf][2] * i1, o[nf][3] * i1);
        *(float2*)&O[((size_t)(bidx * T_ + row)) * C_ + col] = v0;
        *(float2*)&O[((size_t)(bidx * T_ + row + 8)) * C_ + col] = v1;
    }
}

// ===========================================================================
// Launch
// ===========================================================================
extern "C" void kernel_launch(void* const* d_in, const int* in_sizes, int n_in,
                              void* d_out, int out_size)
{
    const float* x   = (const float*)d_in[0];
    const float* ctx = (const float*)d_in[1];
    const float* Wq  = (const float*)d_in[2];
    const float* bq  = (const float*)d_in[3];
    const float* Wk  = (const float*)d_in[4];
    const float* bk  = (const float*)d_in[5];
    const float* Wv  = (const float*)d_in[6];
    const float* bv  = (const float*)d_in[7];
    const float* Wo  = (const float*)d_in[8];
    const float* bo  = (const float*)d_in[9];
    float* out = (float*)d_out;

    float *Qp, *Kp, *Vp, *AOp;
    cudaGetSymbolAddress((void**)&Qp,  g_Q);
    cudaGetSymbolAddress((void**)&Kp,  g_K);
    cudaGetSymbolAddress((void**)&Vp,  g_V);
    cudaGetSymbolAddress((void**)&AOp, g_AO);

    dim3 qkvGrid(C_ / 64, (B_ * T_) / 128, 3);  // (8, 64, 3)
    gemm_qkv_kernel<<<qkvGrid, 256>>>(x, ctx, Wq, bq, Wk, bk, Wv, bv, Qp, Kp, Vp);

    dim3 attnGrid(T_ / 128, B_ * H_);           // (16, 64)
    attn_mma_kernel<<<attnGrid, 256>>>(Qp, Kp, Vp, AOp);

    dim3 gemmGrid(C_ / 64, (B_ * T_) / 128);    // (8, 64)
    gemm_out_kernel<<<gemmGrid, 256>>>(AOp, Wo, bo, out);
}